// round 2
// baseline (speedup 1.0000x reference)
#include <cuda_runtime.h>
#include <math.h>

#define NB   4096   // batch
#define LLn  64     // sequence length
#define HHn  64     // hidden
#define FFn  128    // ffn hidden
#define NLn  2      // layers

struct Smem {
    float X[64*64];    // activations x
    float G[64*64];    // group matrix g (prior across layers)
    float A[64*64];    // scratch (LN out / attention probs)
    float Bf[64*64];   // scratch (Q / O)
    float CD[64*128];  // scratch (K ; V) or FFN hidden (64x128)
    float m0[64];      // mask
    float dv[64];      // digit values
    float isd[64];     // is_digit
    float s1[64];      // sup / scores / logits
    float s2[64];      // sdn / exp-work
    float p1[64];      // p_left / left_mask
    float p2[64];      // p_right / right_mask
    float p3[64];      // p_self
    float q1[64];      // nb_diag (mixed)
    float q2[64];      // llog
    float rw[64];
    float cum[64];
    float pooled[64];
    int   tok[64];
    float scal[8];
};

// out[64 x N] = A[64 x K](smem, lda) @ W[K x N](global) + bias, optional relu / residual-add
template<int N, int K, int TN, bool RELU, bool RES>
__device__ __forceinline__ void gemm_tile(const float* __restrict__ A, int lda,
                                          const float* __restrict__ W,
                                          const float* __restrict__ bias,
                                          float* __restrict__ Out, int ldo, int tid)
{
    const int tx = tid & 15, ty = tid >> 4;     // 16 x 16 thread grid
    const int i0 = ty * 4, j0 = tx * TN;
    float acc[4][TN];
    #pragma unroll
    for (int ii = 0; ii < 4; ii++)
        #pragma unroll
        for (int jj = 0; jj < TN; jj++) acc[ii][jj] = 0.f;

    #pragma unroll 4
    for (int k = 0; k < K; k++) {
        float w[TN];
        #pragma unroll
        for (int jj = 0; jj < TN; jj += 4) {
            float4 wv = *(const float4*)&W[k * N + j0 + jj];
            w[jj] = wv.x; w[jj+1] = wv.y; w[jj+2] = wv.z; w[jj+3] = wv.w;
        }
        #pragma unroll
        for (int ii = 0; ii < 4; ii++) {
            float a = A[(i0 + ii) * lda + k];
            #pragma unroll
            for (int jj = 0; jj < TN; jj++) acc[ii][jj] = fmaf(a, w[jj], acc[ii][jj]);
        }
    }
    #pragma unroll
    for (int ii = 0; ii < 4; ii++)
        #pragma unroll
        for (int jj = 0; jj < TN; jj++) {
            float v = acc[ii][jj] + bias[j0 + jj];
            if (RELU) v = fmaxf(v, 0.f);
            if (RES)  Out[(i0 + ii) * ldo + j0 + jj] += v;
            else      Out[(i0 + ii) * ldo + j0 + jj]  = v;
        }
}

// LayerNorm over last dim (64). 4 threads per row.
__device__ __forceinline__ void layernorm(const float* __restrict__ X,
                                          const float* __restrict__ g,
                                          const float* __restrict__ b,
                                          float* __restrict__ Out, int tid)
{
    const int r = tid >> 2, c0 = (tid & 3) * 16;
    float s = 0.f;
    #pragma unroll
    for (int c = 0; c < 16; c++) s += X[r * 64 + c0 + c];
    s += __shfl_xor_sync(0xffffffffu, s, 1);
    s += __shfl_xor_sync(0xffffffffu, s, 2);
    const float mu = s * (1.f / 64.f);
    float v = 0.f;
    #pragma unroll
    for (int c = 0; c < 16; c++) { float d = X[r * 64 + c0 + c] - mu; v += d * d; }
    v += __shfl_xor_sync(0xffffffffu, v, 1);
    v += __shfl_xor_sync(0xffffffffu, v, 2);
    const float rstd = rsqrtf(v * (1.f / 64.f) + 1e-6f);
    #pragma unroll
    for (int c = 0; c < 16; c++) {
        int cc = c0 + c;
        Out[r * 64 + cc] = g[cc] * (X[r * 64 + cc] - mu) * rstd + b[cc];
    }
}

__global__ __launch_bounds__(256, 2) void fsa_kernel(
    const int*   __restrict__ tok_g,
    const float* __restrict__ emb,
    const float* __restrict__ np_w,   const float* __restrict__ np_b,
    const float* __restrict__ grp_wq, const float* __restrict__ grp_bq,
    const float* __restrict__ grp_wk, const float* __restrict__ grp_bk,
    const float* __restrict__ grp_ln_g, const float* __restrict__ grp_ln_b,
    const float* __restrict__ attn_w, const float* __restrict__ attn_b,
    const float* __restrict__ ln1_g,  const float* __restrict__ ln1_b,
    const float* __restrict__ ln2_g,  const float* __restrict__ ln2_b,
    const float* __restrict__ ffn_w1, const float* __restrict__ ffn_b1,
    const float* __restrict__ ffn_w2, const float* __restrict__ ffn_b2,
    const float* __restrict__ enc_g,  const float* __restrict__ enc_b,
    const float* __restrict__ red_w,  const float* __restrict__ red_b,
    const float* __restrict__ opc_w,  const float* __restrict__ opc_b,
    const float* __restrict__ res_w,  const float* __restrict__ res_b,
    float* __restrict__ out, int out_size)
{
    extern __shared__ float smraw[];
    Smem& sm = *reinterpret_cast<Smem*>(smraw);
    const int b   = blockIdx.x;
    const int tid = threadIdx.x;

    // ---------------- token features ----------------
    if (tid < 64) {
        int t = tok_g[b * 64 + tid];
        sm.tok[tid] = t;
        sm.m0[tid]  = (t != 0) ? 1.f : 0.f;
        float isd   = (t >= 4 && t <= 13) ? 1.f : 0.f;
        sm.isd[tid] = isd;
        sm.dv[tid]  = ((float)t - 4.f) * isd;
    }
    __syncthreads();

    // ---------------- x = emb*sqrt(H) + feat@np_w + np_b + PE ----------------
    {
        const int r = tid >> 2, c0 = (tid & 3) * 16;
        const int t = sm.tok[r];
        const float isd  = sm.isd[r];
        const float dvv  = sm.dv[r];
        const float isop = (t >= 14 && t <= 17) ? 1.f : 0.f;
        const float opt  = isop * ((float)t - 13.f);
        const float* erow = emb + t * 64;
        const float kfreq = (float)(-9.210340371976184 / 64.0); // -ln(10000)/64
        #pragma unroll 4
        for (int c = 0; c < 16; c++) {
            int cc = c0 + c;
            float base = erow[cc] * 8.f
                       + dvv  * np_w[cc]       + isd  * np_w[64 + cc]
                       + opt  * np_w[128 + cc] + isop * np_w[192 + cc]
                       + np_b[cc];
            float freq = expf((float)(cc & ~1) * kfreq);
            float ang  = (float)r * freq;
            float pe   = (cc & 1) ? cosf(ang) : sinf(ang);
            sm.X[r * 64 + cc] = base + pe;
        }
    }
    __syncthreads();

    // ================= layers =================
    for (int l = 0; l < NLn; l++) {
        // ---- group (constituent) attention: build g ----
        layernorm(sm.X, grp_ln_g + l * 64, grp_ln_b + l * 64, sm.A, tid);
        __syncthreads();
        gemm_tile<64,64,4,false,false>(sm.A, 64, grp_wq + l * 4096, grp_bq + l * 64, sm.Bf, 64, tid); // Q
        gemm_tile<64,64,4,false,false>(sm.A, 64, grp_wk + l * 4096, grp_bk + l * 64, sm.CD, 64, tid); // K
        __syncthreads();
        // tridiagonal scores: sup[i]=s[i][i+1], sdn[i]=s[i+1][i]
        if (tid < 63) {
            const float* q = sm.Bf + tid * 64;
            const float* k = sm.CD + (tid + 1) * 64;
            float d = 0.f;
            #pragma unroll 8
            for (int h = 0; h < 64; h++) d = fmaf(q[h], k[h], d);
            sm.s1[tid] = d * 0.125f;
        } else if (tid >= 64 && tid < 127) {
            int i = tid - 64;
            const float* q = sm.Bf + (i + 1) * 64;
            const float* k = sm.CD + i * 64;
            float d = 0.f;
            #pragma unroll 8
            for (int h = 0; h < 64; h++) d = fmaf(q[h], k[h], d);
            sm.s2[i] = d * 0.125f;
        }
        __syncthreads();
        // per-row neighbor softmax (only entries ever consumed downstream)
        if (tid < 64) {
            const int i = tid;
            const bool vL = (i > 0)  && sm.m0[i] > 0.f && sm.m0[i-1] > 0.f;
            const bool vR = (i < 63) && sm.m0[i] > 0.f && sm.m0[i+1] > 0.f;
            float pl, pr, ps;
            if (!vL && !vR) { pl = pr = ps = 1.f / 64.f; }   // all -1e9 -> uniform
            else {
                float sL = vL ? sm.s2[i-1] : -3.4e38f;
                float sR = vR ? sm.s1[i]   : -3.4e38f;
                float m  = fmaxf(sL, sR);
                float eL = vL ? expf(sL - m) : 0.f;
                float eR = vR ? expf(sR - m) : 0.f;
                float Z  = eL + eR;
                pl = eL / Z; pr = eR / Z; ps = 0.f;
            }
            sm.p1[i] = pl; sm.p2[i] = pr; sm.p3[i] = ps;
        }
        __syncthreads();
        // nb (tridiag) + prior mixing (read G before overwrite)
        if (tid < 64) {
            const int i = tid;
            float nbd = sqrtf(sm.p3[i] * sm.p3[i] + 1e-9f);
            if (l > 0) { float pp = sm.G[i * 65]; nbd = pp + (1.f - pp) * nbd; }
            sm.q1[i] = nbd;
            if (i < 63) {
                float nbu = sqrtf(sm.p2[i] * sm.p1[i + 1] + 1e-9f);
                if (l > 0) { float pp = sm.G[i * 64 + i + 1]; nbu = pp + (1.f - pp) * nbu; }
                sm.q2[i] = logf(nbu + 1e-9f);
            }
        }
        __syncthreads();
        // g[i][j>i] = exp(sum llog[i..j-1]) + 1e-9 ; symmetric ; diag = nb_diag
        if (tid < 64) {
            const int i = tid;
            sm.G[i * 65] = sm.q1[i];
            float acc = 0.f;
            for (int j = i + 1; j < 64; j++) {
                acc += sm.q2[j - 1];
                float v = expf(acc) + 1e-9f;
                sm.G[i * 64 + j] = v;
                sm.G[j * 64 + i] = v;
            }
        }
        __syncthreads();

        // ---- multi-head attention (weighted by g) ----
        layernorm(sm.X, ln1_g + l * 64, ln1_b + l * 64, sm.A, tid);
        __syncthreads();
        gemm_tile<64,64,4,false,false>(sm.A, 64, attn_w + (l*4+0)*4096, attn_b + (l*4+0)*64, sm.Bf,        64, tid); // Q
        gemm_tile<64,64,4,false,false>(sm.A, 64, attn_w + (l*4+1)*4096, attn_b + (l*4+1)*64, sm.CD,        64, tid); // K
        gemm_tile<64,64,4,false,false>(sm.A, 64, attn_w + (l*4+2)*4096, attn_b + (l*4+2)*64, sm.CD + 4096, 64, tid); // V
        __syncthreads();
        #pragma unroll 1
        for (int h = 0; h < 4; h++) {
            {   // P = softmax(QK^T/4 masked) * g   -> sm.A
                const int r = tid >> 2, seg = tid & 3;
                float q[16];
                const float* qp = sm.Bf + r * 64 + h * 16;
                #pragma unroll
                for (int d = 0; d < 16; d++) q[d] = qp[d];
                float sc[16]; float mx = -3.4e38f;
                #pragma unroll
                for (int jj = 0; jj < 16; jj++) {
                    int j = seg * 16 + jj;
                    float sv;
                    if (sm.m0[j] > 0.f) {
                        const float* kp = sm.CD + j * 64 + h * 16;
                        float d0 = 0.f;
                        #pragma unroll
                        for (int d = 0; d < 16; d++) d0 = fmaf(q[d], kp[d], d0);
                        sv = d0 * 0.25f;
                    } else sv = -1e9f;
                    sc[jj] = sv; mx = fmaxf(mx, sv);
                }
                mx = fmaxf(mx, __shfl_xor_sync(0xffffffffu, mx, 1));
                mx = fmaxf(mx, __shfl_xor_sync(0xffffffffu, mx, 2));
                float sum = 0.f;
                #pragma unroll
                for (int jj = 0; jj < 16; jj++) { float e = expf(sc[jj] - mx); sc[jj] = e; sum += e; }
                sum += __shfl_xor_sync(0xffffffffu, sum, 1);
                sum += __shfl_xor_sync(0xffffffffu, sum, 2);
                const float inv = 1.f / sum;
                #pragma unroll
                for (int jj = 0; jj < 16; jj++) {
                    int j = seg * 16 + jj;
                    sm.A[r * 64 + j] = sc[jj] * inv * sm.G[r * 64 + j];
                }
            }
            __syncthreads();
            {   // O_h = P @ V_h  -> write into Bf head-h columns (Q head-h dead)
                const int i = tid >> 2, d0 = (tid & 3) * 4;
                float a0 = 0.f, a1 = 0.f, a2 = 0.f, a3 = 0.f;
                const float* V = sm.CD + 4096;
                #pragma unroll 8
                for (int j = 0; j < 64; j++) {
                    float p = sm.A[i * 64 + j];
                    float4 v = *(const float4*)&V[j * 64 + h * 16 + d0];
                    a0 = fmaf(p, v.x, a0); a1 = fmaf(p, v.y, a1);
                    a2 = fmaf(p, v.z, a2); a3 = fmaf(p, v.w, a3);
                }
                float* op = sm.Bf + i * 64 + h * 16 + d0;
                op[0] = a0; op[1] = a1; op[2] = a2; op[3] = a3;
            }
            __syncthreads();
        }
        // x += O @ Wo + bo
        gemm_tile<64,64,4,false,true>(sm.Bf, 64, attn_w + (l*4+3)*4096, attn_b + (l*4+3)*64, sm.X, 64, tid);
        __syncthreads();

        // ---- FFN ----
        layernorm(sm.X, ln2_g + l * 64, ln2_b + l * 64, sm.A, tid);
        __syncthreads();
        gemm_tile<128,64,8,true,false>(sm.A, 64, ffn_w1 + l * 64 * 128, ffn_b1 + l * 128, sm.CD, 128, tid);
        __syncthreads();
        gemm_tile<64,128,4,false,true>(sm.CD, 128, ffn_w2 + l * 128 * 64, ffn_b2 + l * 64, sm.X, 64, tid);
        __syncthreads();
    }

    // ================= readout =================
    layernorm(sm.X, enc_g, enc_b, sm.A, tid);
    __syncthreads();
    if (tid < 64) {
        float s = red_b[0];
        const float* xr = sm.A + tid * 64;
        #pragma unroll 8
        for (int h2 = 0; h2 < 64; h2++) s = fmaf(xr[h2], red_w[h2], s);
        s += (1.f - sm.m0[tid]) * (-1e9f);
        sm.s1[tid] = s;
    }
    __syncthreads();
    if (tid == 0) {
        float m = -3.4e38f;
        for (int i = 0; i < 64; i++) m = fmaxf(m, sm.s1[i]);
        sm.scal[0] = m;
    }
    __syncthreads();
    if (tid < 64) sm.s2[tid] = expf(sm.s1[tid] - sm.scal[0]);
    __syncthreads();
    if (tid == 0) {
        float Z = 0.f;
        for (int i = 0; i < 64; i++) Z += sm.s2[i];
        sm.scal[1] = Z;
    }
    __syncthreads();
    if (tid < 64) sm.rw[tid] = sm.s2[tid] / sm.scal[1];
    __syncthreads();
    if (tid == 0) {
        float c = 0.f;
        for (int i = 0; i < 64; i++) { c += sm.rw[i]; sm.cum[i] = c; }
    }
    __syncthreads();
    if (tid < 64) {
        sm.p1[tid] = (1.f - sm.cum[tid]) * sm.isd[tid];               // left_mask
        sm.p2[tid] = (sm.cum[tid] - sm.rw[tid]) * sm.isd[tid];        // right_mask
    }
    if (tid >= 64 && tid < 128) {       // pooled[h] = sum_l x[l][h] * rw[l]
        int h = tid - 64;
        float p = 0.f;
        #pragma unroll 8
        for (int ll = 0; ll < 64; ll++) p = fmaf(sm.A[ll * 64 + h], sm.rw[ll], p);
        sm.pooled[h] = p;
    }
    __syncthreads();
    if (tid == 0) {
        // soft base-10 assembly
        float lv, rv;
        {
            float tot = 0.f; for (int i = 0; i < 64; i++) tot += sm.p1[i];
            float run = 0.f, acc = 0.f;
            for (int i = 0; i < 64; i++) {
                float smk = sm.p1[i];
                run += smk;
                float w = exp10f((tot - run) * smk) * smk;
                acc = fmaf(sm.dv[i], w, acc);
            }
            lv = acc;
        }
        {
            float tot = 0.f; for (int i = 0; i < 64; i++) tot += sm.p2[i];
            float run = 0.f, acc = 0.f;
            for (int i = 0; i < 64; i++) {
                float smk = sm.p2[i];
                run += smk;
                float w = exp10f((tot - run) * smk) * smk;
                acc = fmaf(sm.dv[i], w, acc);
            }
            rv = acc;
        }
        float lg[4];
        for (int o = 0; o < 4; o++) {
            float a = opc_b[o];
            for (int h = 0; h < 64; h++) a = fmaf(sm.pooled[h], opc_w[h * 4 + o], a);
            lg[o] = a;
        }
        int op = 0; float bm = lg[0];
        for (int o = 1; o < 4; o++) if (lg[o] > bm) { bm = lg[o]; op = o; }
        float result, valid = 1.f;
        if      (op == 0) result = lv + rv;
        else if (op == 1) result = lv - rv;
        else if (op == 2) result = lv * rv;
        else {
            bool bad = fabsf(rv) < 1e-6f;
            result = bad ? 0.f : lv / rv;
            valid  = bad ? 0.f : 1.f;
        }
        float sgn = (result > 0.f) ? 1.f : ((result < 0.f) ? -1.f : 0.f);
        float rc  = sgn * log1pf(fabsf(result));
        sm.scal[2] = result; sm.scal[3] = valid; sm.scal[4] = rc;
        sm.scal[5] = lv;     sm.scal[6] = rv;
        sm.s1[0] = lg[0]; sm.s1[1] = lg[1]; sm.s1[2] = lg[2]; sm.s1[3] = lg[3];
    }
    __syncthreads();

    // outputs: concat(result, result_embedding, valid, left, right, op_logits, rw)
    const bool full = (out_size >= 136 * NB);
    if (full) {
        if (tid == 0) {
            out[b]           = sm.scal[2];
            out[65*NB + b]   = sm.scal[3];
            out[66*NB + b]   = sm.scal[5];
            out[67*NB + b]   = sm.scal[6];
            #pragma unroll
            for (int o = 0; o < 4; o++) out[68*NB + b*4 + o] = sm.s1[o];
        }
        if (tid < 64) {
            float rc = sm.scal[4], valid = sm.scal[3];
            out[NB + b*64 + tid]    = rc * res_w[tid] + valid * res_w[64 + tid] + res_b[tid];
            out[72*NB + b*64 + tid] = sm.rw[tid];
        }
    } else {
        if (tid == 0) out[b] = sm.scal[2];
    }
}

extern "C" void kernel_launch(void* const* d_in, const int* in_sizes, int n_in,
                              void* d_out, int out_size)
{
    const size_t shmem = sizeof(Smem);
    cudaFuncSetAttribute(fsa_kernel, cudaFuncAttributeMaxDynamicSharedMemorySize, (int)shmem);
    fsa_kernel<<<NB, 256, shmem>>>(
        (const int*)  d_in[0],  (const float*)d_in[1],
        (const float*)d_in[2],  (const float*)d_in[3],
        (const float*)d_in[4],  (const float*)d_in[5],
        (const float*)d_in[6],  (const float*)d_in[7],
        (const float*)d_in[8],  (const float*)d_in[9],
        (const float*)d_in[10], (const float*)d_in[11],
        (const float*)d_in[12], (const float*)d_in[13],
        (const float*)d_in[14], (const float*)d_in[15],
        (const float*)d_in[16], (const float*)d_in[17],
        (const float*)d_in[18], (const float*)d_in[19],
        (const float*)d_in[20], (const float*)d_in[21],
        (const float*)d_in[22], (const float*)d_in[23],
        (const float*)d_in[24], (const float*)d_in[25],
        (const float*)d_in[26], (const float*)d_in[27],
        (float*)d_out, out_size);
}

// round 4
// speedup vs baseline: 1.3291x; 1.3291x over previous
#include <cuda_runtime.h>
#include <math.h>

#define NB   4096   // batch
#define LD   68     // padded row stride (floats) for 64-wide matrices
#define LDF  132    // padded row stride for FFN hidden (128-wide)

typedef unsigned long long ull;

__device__ __forceinline__ ull pack2(float x, float y) {
    ull r; asm("mov.b64 %0, {%1, %2};" : "=l"(r) : "f"(x), "f"(y)); return r;
}
__device__ __forceinline__ float2 unpack2(ull v) {
    float2 r; asm("mov.b64 {%0, %1}, %2;" : "=f"(r.x), "=f"(r.y) : "l"(v)); return r;
}
__device__ __forceinline__ ull ffma2(ull a, ull b, ull c) {
    ull r; asm("fma.rn.f32x2 %0, %1, %2, %3;" : "=l"(r) : "l"(a), "l"(b), "l"(c)); return r;
}
__device__ __forceinline__ float ex2f(float x) {
    float r; asm("ex2.approx.f32 %0, %1;" : "=f"(r) : "f"(x)); return r;
}
__device__ __forceinline__ float lg2f_(float x) {
    float r; asm("lg2.approx.f32 %0, %1;" : "=f"(r) : "f"(x)); return r;
}

#define LOG2E    1.4426950408889634f
#define LOG2_10  3.3219280948873623f
#define SGRP     (0.125f * LOG2E)   // 1/sqrt(64) folded with log2e
#define SATT     (0.25f  * LOG2E)   // 1/sqrt(16) folded with log2e

struct Smem {
    float X [64*LD];     // activations
    float G [64*LD];     // group matrix (prior across layers)
    float A [64*LD];     // LN out / attention probs
    float Bf[64*LD];     // Q / O
    float KV[2*64*LD];   // K ; V  (FFN hidden uses ld=LDF, 64*132=8448 <= 8704)
    float m0[64], dv[64], isd[64];
    float s1[64], s2[64];          // tridiag scores / readout scores / logits
    float q1[64], q2[64], S[64];   // nb diag, llog, prefix sums
    float rw[64], cum[64], pooled[64], pmL[64], pmR[64];
    int   tok[64];
    float scal[8];
};

// Out[64 x 64] = A[64 x K] @ W[K x 64 (row-stride ldw)] + bias, opt relu / residual.
// 16x16 thread grid, 4x4 tile per thread, f32x2 packed FMA (pairs over k).
template<int K, bool RELU, bool RES>
__device__ __forceinline__ void gemm64(const float* __restrict__ Am, int lda,
                                       const float* __restrict__ W, int ldw,
                                       const float* __restrict__ bias,
                                       float* __restrict__ Out, int ldo, int tid)
{
    const int tx = tid & 15, ty = tid >> 4;
    const int i0 = ty * 4, j0 = tx * 4;
    ull acc[4][4];
    #pragma unroll
    for (int ii = 0; ii < 4; ii++)
        #pragma unroll
        for (int jj = 0; jj < 4; jj++) acc[ii][jj] = 0ull;

    #pragma unroll 4
    for (int k = 0; k < K; k += 4) {
        float4 a4[4];
        #pragma unroll
        for (int ii = 0; ii < 4; ii++)
            a4[ii] = *(const float4*)(Am + (i0 + ii) * lda + k);
        float4 w0 = *(const float4*)(W + (k + 0) * ldw + j0);
        float4 w1 = *(const float4*)(W + (k + 1) * ldw + j0);
        float4 w2 = *(const float4*)(W + (k + 2) * ldw + j0);
        float4 w3 = *(const float4*)(W + (k + 3) * ldw + j0);
        ull wp0[4], wp1[4];
        wp0[0] = pack2(w0.x, w1.x); wp0[1] = pack2(w0.y, w1.y);
        wp0[2] = pack2(w0.z, w1.z); wp0[3] = pack2(w0.w, w1.w);
        wp1[0] = pack2(w2.x, w3.x); wp1[1] = pack2(w2.y, w3.y);
        wp1[2] = pack2(w2.z, w3.z); wp1[3] = pack2(w2.w, w3.w);
        #pragma unroll
        for (int ii = 0; ii < 4; ii++) {
            ull a01 = pack2(a4[ii].x, a4[ii].y);
            ull a23 = pack2(a4[ii].z, a4[ii].w);
            #pragma unroll
            for (int jj = 0; jj < 4; jj++) {
                acc[ii][jj] = ffma2(a01, wp0[jj], acc[ii][jj]);
                acc[ii][jj] = ffma2(a23, wp1[jj], acc[ii][jj]);
            }
        }
    }
    float4 bv = *(const float4*)(bias + j0);
    #pragma unroll
    for (int ii = 0; ii < 4; ii++) {
        float2 p0 = unpack2(acc[ii][0]);
        float2 p1 = unpack2(acc[ii][1]);
        float2 p2 = unpack2(acc[ii][2]);
        float2 p3 = unpack2(acc[ii][3]);
        float4 st;
        st.x = p0.x + p0.y + bv.x;
        st.y = p1.x + p1.y + bv.y;
        st.z = p2.x + p2.y + bv.z;
        st.w = p3.x + p3.y + bv.w;
        if (RELU) {
            st.x = fmaxf(st.x, 0.f); st.y = fmaxf(st.y, 0.f);
            st.z = fmaxf(st.z, 0.f); st.w = fmaxf(st.w, 0.f);
        }
        float* op = Out + (i0 + ii) * ldo + j0;
        if (RES) {
            float4 old = *(float4*)op;
            st.x += old.x; st.y += old.y; st.z += old.z; st.w += old.w;
        }
        *(float4*)op = st;
    }
}

// LayerNorm over 64, 4 threads per row, vectorized (no pointer aliasing of regs!)
__device__ __forceinline__ void layernorm(const float* __restrict__ Xm,
                                          const float* __restrict__ g,
                                          const float* __restrict__ bb,
                                          float* __restrict__ Out, int tid)
{
    const int r = tid >> 2, c0 = (tid & 3) * 16;
    const float4* xr = (const float4*)(Xm + r * LD + c0);
    float4 v0 = xr[0], v1 = xr[1], v2 = xr[2], v3 = xr[3];
    float s = v0.x+v0.y+v0.z+v0.w + v1.x+v1.y+v1.z+v1.w
            + v2.x+v2.y+v2.z+v2.w + v3.x+v3.y+v3.z+v3.w;
    s += __shfl_xor_sync(0xffffffffu, s, 1);
    s += __shfl_xor_sync(0xffffffffu, s, 2);
    const float mu = s * (1.f / 64.f);
    float var = 0.f;
    {
        float d;
        d = v0.x - mu; var += d*d;  d = v0.y - mu; var += d*d;
        d = v0.z - mu; var += d*d;  d = v0.w - mu; var += d*d;
        d = v1.x - mu; var += d*d;  d = v1.y - mu; var += d*d;
        d = v1.z - mu; var += d*d;  d = v1.w - mu; var += d*d;
        d = v2.x - mu; var += d*d;  d = v2.y - mu; var += d*d;
        d = v2.z - mu; var += d*d;  d = v2.w - mu; var += d*d;
        d = v3.x - mu; var += d*d;  d = v3.y - mu; var += d*d;
        d = v3.z - mu; var += d*d;  d = v3.w - mu; var += d*d;
    }
    var += __shfl_xor_sync(0xffffffffu, var, 1);
    var += __shfl_xor_sync(0xffffffffu, var, 2);
    const float rstd = rsqrtf(var * (1.f / 64.f) + 1e-6f);
    const float4* gp = (const float4*)(g + c0);
    const float4* bp = (const float4*)(bb + c0);
    float4* op = (float4*)(Out + r * LD + c0);
    float4 xv, gv, bv4, ov;
    #pragma unroll
    for (int q = 0; q < 4; q++) {
        xv = (q==0)?v0:((q==1)?v1:((q==2)?v2:v3));
        gv = gp[q]; bv4 = bp[q];
        ov.x = gv.x * (xv.x - mu) * rstd + bv4.x;
        ov.y = gv.y * (xv.y - mu) * rstd + bv4.y;
        ov.z = gv.z * (xv.z - mu) * rstd + bv4.z;
        ov.w = gv.w * (xv.w - mu) * rstd + bv4.w;
        op[q] = ov;
    }
}

__global__ __launch_bounds__(256, 2) void fsa_kernel(
    const int*   __restrict__ tok_g,
    const float* __restrict__ emb,
    const float* __restrict__ np_w,   const float* __restrict__ np_b,
    const float* __restrict__ grp_wq, const float* __restrict__ grp_bq,
    const float* __restrict__ grp_wk, const float* __restrict__ grp_bk,
    const float* __restrict__ grp_ln_g, const float* __restrict__ grp_ln_b,
    const float* __restrict__ attn_w, const float* __restrict__ attn_b,
    const float* __restrict__ ln1_g,  const float* __restrict__ ln1_b,
    const float* __restrict__ ln2_g,  const float* __restrict__ ln2_b,
    const float* __restrict__ ffn_w1, const float* __restrict__ ffn_b1,
    const float* __restrict__ ffn_w2, const float* __restrict__ ffn_b2,
    const float* __restrict__ enc_g,  const float* __restrict__ enc_b,
    const float* __restrict__ red_w,  const float* __restrict__ red_b,
    const float* __restrict__ opc_w,  const float* __restrict__ opc_b,
    const float* __restrict__ res_w,  const float* __restrict__ res_b,
    float* __restrict__ out, int out_size)
{
    extern __shared__ float smraw[];
    Smem& sm = *reinterpret_cast<Smem*>(smraw);
    const int b   = blockIdx.x;
    const int tid = threadIdx.x;

    // ---------------- token features ----------------
    if (tid < 64) {
        int t = tok_g[b * 64 + tid];
        sm.tok[tid] = t;
        sm.m0[tid]  = (t != 0) ? 1.f : 0.f;
        float isd   = (t >= 4 && t <= 13) ? 1.f : 0.f;
        sm.isd[tid] = isd;
        sm.dv[tid]  = ((float)t - 4.f) * isd;
    }
    __syncthreads();

    // ---------------- x = emb*sqrt(H) + feat@np_w + np_b + PE ----------------
    {
        const int r = tid >> 2, c0 = (tid & 3) * 16;
        const int t = sm.tok[r];
        const float isd  = sm.isd[r];
        const float dvv  = sm.dv[r];
        const float isop = (t >= 14 && t <= 17) ? 1.f : 0.f;
        const float opt  = isop * ((float)t - 13.f);
        const float* erow = emb + t * 64;
        const float kfreq = (float)(-9.210340371976184 / 64.0); // -ln(10000)/64
        #pragma unroll 4
        for (int c = 0; c < 16; c++) {
            int cc = c0 + c;
            float base = erow[cc] * 8.f
                       + dvv  * np_w[cc]       + isd  * np_w[64 + cc]
                       + opt  * np_w[128 + cc] + isop * np_w[192 + cc]
                       + np_b[cc];
            float freq = expf((float)(cc & ~1) * kfreq);
            float ang  = (float)r * freq;
            float pe   = (cc & 1) ? cosf(ang) : sinf(ang);
            sm.X[r * LD + cc] = base + pe;
        }
    }
    __syncthreads();

    float* const Kb = sm.KV;
    float* const Vb = sm.KV + 64 * LD;

    // ================= layers =================
    #pragma unroll 1
    for (int l = 0; l < 2; l++) {
        // ---- group attention -> G ----
        layernorm(sm.X, grp_ln_g + l * 64, grp_ln_b + l * 64, sm.A, tid);
        __syncthreads();
        gemm64<64,false,false>(sm.A, LD, grp_wq + l * 4096, 64, grp_bq + l * 64, sm.Bf, LD, tid);
        gemm64<64,false,false>(sm.A, LD, grp_wk + l * 4096, 64, grp_bk + l * 64, Kb,    LD, tid);
        __syncthreads();
        // tridiagonal scores (pre-scaled by log2e/8)
        if (tid < 63 || (tid >= 64 && tid < 127)) {
            int i   = (tid < 63) ? tid : (tid - 64);
            const float4* qp = (const float4*)(sm.Bf + ((tid < 63) ? i : i + 1) * LD);
            const float4* kp = (const float4*)(Kb   + ((tid < 63) ? i + 1 : i) * LD);
            ull acc = 0ull;
            #pragma unroll 4
            for (int m = 0; m < 16; m++) {
                float4 q4 = qp[m], k4 = kp[m];
                acc = ffma2(pack2(q4.x, q4.y), pack2(k4.x, k4.y), acc);
                acc = ffma2(pack2(q4.z, q4.w), pack2(k4.z, k4.w), acc);
            }
            float2 p = unpack2(acc);
            float sv = (p.x + p.y) * SGRP;
            if (tid < 63) sm.s1[i] = sv; else sm.s2[i] = sv;
        }
        __syncthreads();
        // fused neighbor softmax + sqrt-symmetrize + prior mix -> q1 (diag), q2 (llog2)
        if (tid < 64) {
            const int i = tid;
            const float m_i = sm.m0[i];
            bool vL = (i > 0)  && m_i > 0.f && sm.m0[i-1] > 0.f;
            bool vR = (i < 63) && m_i > 0.f && sm.m0[i+1] > 0.f;
            float pr_i, ps_i;
            if (!vL && !vR) { pr_i = 1.f/64.f; ps_i = 1.f/64.f; }
            else {
                float sL = vL ? sm.s2[i-1] : -3.4e38f;
                float sR = vR ? sm.s1[i]   : -3.4e38f;
                float m  = fmaxf(sL, sR);
                float eL = vL ? ex2f(sL - m) : 0.f;
                float eR = vR ? ex2f(sR - m) : 0.f;
                pr_i = eR / (eL + eR); ps_i = 0.f;
            }
            float nbd = sqrtf(ps_i * ps_i + 1e-9f);
            if (l > 0) { float pp = sm.G[i * LD + i]; nbd = pp + (1.f - pp) * nbd; }
            sm.q1[i] = nbd;
            if (i < 63) {
                const int i1 = i + 1;
                bool vL1 = m_i > 0.f && sm.m0[i1] > 0.f;
                bool vR1 = (i1 < 63) && sm.m0[i1] > 0.f && sm.m0[i1+1] > 0.f;
                float pl1;
                if (!vL1 && !vR1) pl1 = 1.f/64.f;
                else {
                    float sL = vL1 ? sm.s2[i]  : -3.4e38f;
                    float sR = vR1 ? sm.s1[i1] : -3.4e38f;
                    float m  = fmaxf(sL, sR);
                    float eL = vL1 ? ex2f(sL - m) : 0.f;
                    float eR = vR1 ? ex2f(sR - m) : 0.f;
                    pl1 = eL / (eL + eR);
                }
                float nbu = sqrtf(pr_i * pl1 + 1e-9f);
                if (l > 0) { float pp = sm.G[i * LD + i1]; nbu = pp + (1.f - pp) * nbu; }
                sm.q2[i] = lg2f_(nbu + 1e-9f);     // log2 for ex2 chain
            }
        }
        __syncthreads();
        if (tid == 0) {           // prefix sums of llog2
            float a = 0.f; sm.S[0] = 0.f;
            for (int j = 1; j < 64; j++) { a += sm.q2[j-1]; sm.S[j] = a; }
        }
        __syncthreads();
        // parallel G fill: g[i][j] = ex2(S[max]-S[min]) + 1e-9 (i!=j), diag = q1
        for (int t = tid; t < 4096; t += 256) {
            int i = t >> 6, j = t & 63;
            float v;
            if (i == j) v = sm.q1[i];
            else {
                int lo = (i < j) ? i : j, hi = (i < j) ? j : i;
                v = ex2f(sm.S[hi] - sm.S[lo]) + 1e-9f;
            }
            sm.G[i * LD + j] = v;
        }
        __syncthreads();

        // ---- multi-head attention weighted by g ----
        layernorm(sm.X, ln1_g + l * 64, ln1_b + l * 64, sm.A, tid);
        __syncthreads();
        gemm64<64,false,false>(sm.A, LD, attn_w + (l*4+0)*4096, 64, attn_b + (l*4+0)*64, sm.Bf, LD, tid);
        gemm64<64,false,false>(sm.A, LD, attn_w + (l*4+1)*4096, 64, attn_b + (l*4+1)*64, Kb,    LD, tid);
        gemm64<64,false,false>(sm.A, LD, attn_w + (l*4+2)*4096, 64, attn_b + (l*4+2)*64, Vb,    LD, tid);
        __syncthreads();
        #pragma unroll 1
        for (int h = 0; h < 4; h++) {
            {   // scores + softmax * g -> sm.A  (j = 4*jj+seg: conflict-free)
                const int r = tid >> 2, seg = tid & 3;
                const float4* qp = (const float4*)(sm.Bf + r * LD + h * 16);
                float4 q0 = qp[0], q1 = qp[1], q2 = qp[2], q3 = qp[3];
                float sc[16]; float mx = -3.4e38f;
                #pragma unroll 4
                for (int jj = 0; jj < 16; jj++) {
                    int j = 4 * jj + seg;
                    float sv;
                    if (sm.m0[j] > 0.f) {
                        const float4* kp = (const float4*)(Kb + j * LD + h * 16);
                        float4 k0 = kp[0], k1 = kp[1], k2 = kp[2], k3 = kp[3];
                        ull acc = 0ull;
                        acc = ffma2(pack2(q0.x,q0.y), pack2(k0.x,k0.y), acc);
                        acc = ffma2(pack2(q0.z,q0.w), pack2(k0.z,k0.w), acc);
                        acc = ffma2(pack2(q1.x,q1.y), pack2(k1.x,k1.y), acc);
                        acc = ffma2(pack2(q1.z,q1.w), pack2(k1.z,k1.w), acc);
                        acc = ffma2(pack2(q2.x,q2.y), pack2(k2.x,k2.y), acc);
                        acc = ffma2(pack2(q2.z,q2.w), pack2(k2.z,k2.w), acc);
                        acc = ffma2(pack2(q3.x,q3.y), pack2(k3.x,k3.y), acc);
                        acc = ffma2(pack2(q3.z,q3.w), pack2(k3.z,k3.w), acc);
                        float2 p = unpack2(acc);
                        sv = (p.x + p.y) * SATT;
                    } else sv = -1e9f;
                    sc[jj] = sv; mx = fmaxf(mx, sv);
                }
                mx = fmaxf(mx, __shfl_xor_sync(0xffffffffu, mx, 1));
                mx = fmaxf(mx, __shfl_xor_sync(0xffffffffu, mx, 2));
                float sum = 0.f;
                #pragma unroll
                for (int jj = 0; jj < 16; jj++) { float e = ex2f(sc[jj] - mx); sc[jj] = e; sum += e; }
                sum += __shfl_xor_sync(0xffffffffu, sum, 1);
                sum += __shfl_xor_sync(0xffffffffu, sum, 2);
                const float inv = 1.f / sum;
                #pragma unroll
                for (int jj = 0; jj < 16; jj++) {
                    int j = 4 * jj + seg;
                    sm.A[r * LD + j] = sc[jj] * inv * sm.G[r * LD + j];
                }
            }
            __syncthreads();
            {   // O_h = P @ V_h  (thread: row i, 4 dims at c*4)
                const int i = tid >> 2, c = tid & 3;
                ull o01 = 0ull, o23 = 0ull;
                const float* vbase = Vb + h * 16 + c * 4;
                const float* prow  = sm.A + i * LD;
                #pragma unroll 4
                for (int jj = 0; jj < 16; jj++) {
                    float4 p4 = *(const float4*)(prow + 4 * jj);
                    {
                        float4 v = *(const float4*)(vbase + (4 * jj + 0) * LD);
                        ull pb = pack2(p4.x, p4.x);
                        o01 = ffma2(pb, pack2(v.x, v.y), o01);
                        o23 = ffma2(pb, pack2(v.z, v.w), o23);
                    }
                    {
                        float4 v = *(const float4*)(vbase + (4 * jj + 1) * LD);
                        ull pb = pack2(p4.y, p4.y);
                        o01 = ffma2(pb, pack2(v.x, v.y), o01);
                        o23 = ffma2(pb, pack2(v.z, v.w), o23);
                    }
                    {
                        float4 v = *(const float4*)(vbase + (4 * jj + 2) * LD);
                        ull pb = pack2(p4.z, p4.z);
                        o01 = ffma2(pb, pack2(v.x, v.y), o01);
                        o23 = ffma2(pb, pack2(v.z, v.w), o23);
                    }
                    {
                        float4 v = *(const float4*)(vbase + (4 * jj + 3) * LD);
                        ull pb = pack2(p4.w, p4.w);
                        o01 = ffma2(pb, pack2(v.x, v.y), o01);
                        o23 = ffma2(pb, pack2(v.z, v.w), o23);
                    }
                }
                float2 a01 = unpack2(o01), a23 = unpack2(o23);
                float4 st; st.x = a01.x; st.y = a01.y; st.z = a23.x; st.w = a23.y;
                *(float4*)(sm.Bf + i * LD + h * 16 + c * 4) = st;
            }
            __syncthreads();
        }
        // x += O @ Wo + bo
        gemm64<64,false,true>(sm.Bf, LD, attn_w + (l*4+3)*4096, 64, attn_b + (l*4+3)*64, sm.X, LD, tid);
        __syncthreads();

        // ---- FFN ----
        layernorm(sm.X, ln2_g + l * 64, ln2_b + l * 64, sm.A, tid);
        __syncthreads();
        gemm64<64,true,false>(sm.A, LD, ffn_w1 + l * 8192,      128, ffn_b1 + l * 128,      sm.KV,      LDF, tid);
        gemm64<64,true,false>(sm.A, LD, ffn_w1 + l * 8192 + 64, 128, ffn_b1 + l * 128 + 64, sm.KV + 64, LDF, tid);
        __syncthreads();
        gemm64<128,false,true>(sm.KV, LDF, ffn_w2 + l * 8192, 64, ffn_b2 + l * 64, sm.X, LD, tid);
        __syncthreads();
    }

    // ================= readout =================
    layernorm(sm.X, enc_g, enc_b, sm.A, tid);
    __syncthreads();
    if (tid < 64) {
        const float4* xr = (const float4*)(sm.A + tid * LD);
        const float4* wr = (const float4*)red_w;
        ull acc = 0ull;
        #pragma unroll 4
        for (int m = 0; m < 16; m++) {
            float4 x4 = xr[m], w4 = wr[m];
            acc = ffma2(pack2(x4.x,x4.y), pack2(w4.x,w4.y), acc);
            acc = ffma2(pack2(x4.z,x4.w), pack2(w4.z,w4.w), acc);
        }
        float2 p = unpack2(acc);
        float s = p.x + p.y + red_b[0];
        s += (1.f - sm.m0[tid]) * (-1e9f);
        sm.s1[tid] = s;
    }
    __syncthreads();
    if (tid == 0) {
        float m = -3.4e38f;
        for (int i = 0; i < 64; i++) m = fmaxf(m, sm.s1[i]);
        sm.scal[0] = m;
    }
    __syncthreads();
    if (tid < 64) sm.s2[tid] = ex2f((sm.s1[tid] - sm.scal[0]) * LOG2E);
    __syncthreads();
    if (tid == 0) {
        float Z = 0.f;
        for (int i = 0; i < 64; i++) Z += sm.s2[i];
        sm.scal[1] = Z;
    }
    __syncthreads();
    if (tid < 64) sm.rw[tid] = sm.s2[tid] / sm.scal[1];
    __syncthreads();
    if (tid == 0) {
        float c = 0.f;
        for (int i = 0; i < 64; i++) { c += sm.rw[i]; sm.cum[i] = c; }
    }
    __syncthreads();
    if (tid < 64) {
        sm.pmL[tid] = (1.f - sm.cum[tid]) * sm.isd[tid];
        sm.pmR[tid] = (sm.cum[tid] - sm.rw[tid]) * sm.isd[tid];
    }
    if (tid >= 64 && tid < 128) {       // pooled[h] = sum_l xln[l][h] * rw[l]
        int h = tid - 64;
        float p = 0.f;
        #pragma unroll 8
        for (int ll = 0; ll < 64; ll++) p = fmaf(sm.A[ll * LD + h], sm.rw[ll], p);
        sm.pooled[h] = p;
    }
    __syncthreads();
    if (tid == 0) {
        float lv, rv;
        {
            float tot = 0.f; for (int i = 0; i < 64; i++) tot += sm.pmL[i];
            float run = 0.f, acc = 0.f;
            for (int i = 0; i < 64; i++) {
                float smk = sm.pmL[i];
                run += smk;
                float w = ex2f((tot - run) * smk * LOG2_10) * smk;
                acc = fmaf(sm.dv[i], w, acc);
            }
            lv = acc;
        }
        {
            float tot = 0.f; for (int i = 0; i < 64; i++) tot += sm.pmR[i];
            float run = 0.f, acc = 0.f;
            for (int i = 0; i < 64; i++) {
                float smk = sm.pmR[i];
                run += smk;
                float w = ex2f((tot - run) * smk * LOG2_10) * smk;
                acc = fmaf(sm.dv[i], w, acc);
            }
            rv = acc;
        }
        float lg[4];
        for (int o = 0; o < 4; o++) {
            float a = opc_b[o];
            for (int h = 0; h < 64; h++) a = fmaf(sm.pooled[h], opc_w[h * 4 + o], a);
            lg[o] = a;
        }
        int op = 0; float bm = lg[0];
        for (int o = 1; o < 4; o++) if (lg[o] > bm) { bm = lg[o]; op = o; }
        float result, valid = 1.f;
        if      (op == 0) result = lv + rv;
        else if (op == 1) result = lv - rv;
        else if (op == 2) result = lv * rv;
        else {
            bool bad = fabsf(rv) < 1e-6f;
            result = bad ? 0.f : lv / rv;
            valid  = bad ? 0.f : 1.f;
        }
        float sgn = (result > 0.f) ? 1.f : ((result < 0.f) ? -1.f : 0.f);
        float rc  = sgn * log1pf(fabsf(result));
        sm.scal[2] = result; sm.scal[3] = valid; sm.scal[4] = rc;
        sm.scal[5] = lv;     sm.scal[6] = rv;
        sm.s1[0] = lg[0]; sm.s1[1] = lg[1]; sm.s1[2] = lg[2]; sm.s1[3] = lg[3];
    }
    __syncthreads();

    // outputs: concat(result, result_embedding, valid, left, right, op_logits, rw)
    const bool full = (out_size >= 136 * NB);
    if (full) {
        if (tid == 0) {
            out[b]           = sm.scal[2];
            out[65*NB + b]   = sm.scal[3];
            out[66*NB + b]   = sm.scal[5];
            out[67*NB + b]   = sm.scal[6];
            #pragma unroll
            for (int o = 0; o < 4; o++) out[68*NB + b*4 + o] = sm.s1[o];
        }
        if (tid < 64) {
            float rc = sm.scal[4], valid = sm.scal[3];
            out[NB + b*64 + tid]    = rc * res_w[tid] + valid * res_w[64 + tid] + res_b[tid];
            out[72*NB + b*64 + tid] = sm.rw[tid];
        }
    } else {
        if (tid == 0) out[b] = sm.scal[2];
    }
}

extern "C" void kernel_launch(void* const* d_in, const int* in_sizes, int n_in,
                              void* d_out, int out_size)
{
    const size_t shmem = sizeof(Smem);
    cudaFuncSetAttribute(fsa_kernel, cudaFuncAttributeMaxDynamicSharedMemorySize, (int)shmem);
    fsa_kernel<<<NB, 256, shmem>>>(
        (const int*)  d_in[0],  (const float*)d_in[1],
        (const float*)d_in[2],  (const float*)d_in[3],
        (const float*)d_in[4],  (const float*)d_in[5],
        (const float*)d_in[6],  (const float*)d_in[7],
        (const float*)d_in[8],  (const float*)d_in[9],
        (const float*)d_in[10], (const float*)d_in[11],
        (const float*)d_in[12], (const float*)d_in[13],
        (const float*)d_in[14], (const float*)d_in[15],
        (const float*)d_in[16], (const float*)d_in[17],
        (const float*)d_in[18], (const float*)d_in[19],
        (const float*)d_in[20], (const float*)d_in[21],
        (const float*)d_in[22], (const float*)d_in[23],
        (const float*)d_in[24], (const float*)d_in[25],
        (const float*)d_in[26], (const float*)d_in[27],
        (float*)d_out, out_size);
}